// round 15
// baseline (speedup 1.0000x reference)
#include <cuda_runtime.h>
#include <cuda_bf16.h>
#include <cuda_fp16.h>
#include <cstdint>
#include <stdint.h>
#include <math.h>

// Problem constants
#define NB 128
#define NN 32
#define NLW 36
#define DS 512
#define DV 1024
#define HH 512
#define NP 496
#define NNL (NN*NLW)      // 1152
#define BNROWS (NB*NN)    // 4096
#define BPROWS (NB*NP)    // 63488
#define NBC 8              // base chunks of 64 over K=512

// ---- scratch (__device__ globals; no runtime allocation) ----
__device__ __nv_bfloat16 g_Ball[(size_t)2048 * 1024];   // [Wg^T;W1a^T;W1b^T] (hi|lo) bf16
__device__ __half g_W1ct[(size_t)HH * 512];             // W1c^T fp16
__device__ __half g_W2t [(size_t)HH * 512];             // W2^T  fp16
__device__ __half g_H1  [(size_t)BPROWS * HH];          // H1 fp16
__device__ float g_GUV[(size_t)BNROWS * 2048];          // [G | U | V] fp32
__device__ float g_tpart[(size_t)2 * BPROWS];
__device__ float g_M[NB * NNL];
__device__ float g_Avec[NB * NLW];
__device__ float g_cs[NB];
__device__ float g_ci[NB];
__device__ float g_Msum[NB];
__device__ float g_sent[NB * NB];
__device__ int   g_iu[NP];
__device__ int   g_ju[NP];

// =============================================================
// helpers
// =============================================================
__device__ __forceinline__ uint32_t s2u(const void* p) {
    uint32_t a;
    asm("{ .reg .u64 t; cvta.to.shared.u64 t, %1; cvt.u32.u64 %0, t; }" : "=r"(a) : "l"(p));
    return a;
}
__device__ __forceinline__ void ldsm_x4(uint32_t* r, uint32_t addr) {
    asm volatile("ldmatrix.sync.aligned.m8n8.x4.shared.b16 {%0,%1,%2,%3}, [%4];"
        : "=r"(r[0]), "=r"(r[1]), "=r"(r[2]), "=r"(r[3]) : "r"(addr));
}
__device__ __forceinline__ void mma16816(float* c, const uint32_t* a, uint32_t b0, uint32_t b1) {
    asm volatile(
        "mma.sync.aligned.m16n8k16.row.col.f32.bf16.bf16.f32 "
        "{%0,%1,%2,%3}, {%4,%5,%6,%7}, {%8,%9}, {%0,%1,%2,%3};"
        : "+f"(c[0]), "+f"(c[1]), "+f"(c[2]), "+f"(c[3])
        : "r"(a[0]), "r"(a[1]), "r"(a[2]), "r"(a[3]), "r"(b0), "r"(b1));
}
__device__ __forceinline__ void mma16816h(float* c, const uint32_t* a, uint32_t b0, uint32_t b1) {
    asm volatile(
        "mma.sync.aligned.m16n8k16.row.col.f32.f16.f16.f32 "
        "{%0,%1,%2,%3}, {%4,%5,%6,%7}, {%8,%9}, {%0,%1,%2,%3};"
        : "+f"(c[0]), "+f"(c[1]), "+f"(c[2]), "+f"(c[3])
        : "r"(a[0]), "r"(a[1]), "r"(a[2]), "r"(a[3]), "r"(b0), "r"(b1));
}
#define CPASYNC16(dst, src) asm volatile("cp.async.cg.shared.global [%0], [%1], 16;" :: "r"(dst), "l"(src))
#define CPCOMMIT()          asm volatile("cp.async.commit_group;" ::: "memory")
#define CPWAIT3()           asm volatile("cp.async.wait_group 3;" ::: "memory")
#define CPWAIT2()           asm volatile("cp.async.wait_group 2;" ::: "memory")
#define CPWAIT1()           asm volatile("cp.async.wait_group 1;" ::: "memory")
#define CPWAIT0()           asm volatile("cp.async.wait_group 0;" ::: "memory")

__device__ __forceinline__ void split2(float v, __nv_bfloat16& h, __nv_bfloat16& l) {
    h = __float2bfloat16(v);
    l = __float2bfloat16(v - __bfloat162float(h));
}
// bf16 pair split
__device__ __forceinline__ void pack2(float a, float b, uint32_t& hi, uint32_t& lo) {
    __nv_bfloat16 ha, la, hb, lb;
    split2(a, ha, la); split2(b, hb, lb);
    __nv_bfloat162 h = __halves2bfloat162(ha, hb);
    __nv_bfloat162 l = __halves2bfloat162(la, lb);
    hi = *(uint32_t*)&h; lo = *(uint32_t*)&l;
}
// fp16 pair (hi only)
__device__ __forceinline__ uint32_t packh(float a, float b) {
    __half2 h = __halves2half2(__float2half_rn(a), __float2half_rn(b));
    return *(uint32_t*)&h;
}

// =============================================================
// Prep kernels
// =============================================================
__global__ void k_init_pairs() {
    int p = threadIdx.x;
    if (p >= NP) return;
    int cum = 0;
    for (int i = 0; i < NN; i++) {
        int cnt = NN - 1 - i;
        if (p < cum + cnt) { g_iu[p] = i; g_ju[p] = i + 1 + (p - cum); return; }
        cum += cnt;
    }
}
// B layout per row (1024 cols, bf16): [0,512)=hi, [512,1024)=lo
__device__ __forceinline__ void store_b2(__nv_bfloat16* row, int c, float v) {
    __nv_bfloat16 h, l; split2(v, h, l);
    row[c] = h; row[512 + c] = l;
}
__global__ void k_prep_Ball(const float* __restrict__ Wg, const float* __restrict__ W1) {
    int n = blockIdx.x;                 // 2048
    int c0 = threadIdx.x * 4;           // 128 thr
    __nv_bfloat16* row = g_Ball + (size_t)n * 1024;
    #pragma unroll
    for (int t = 0; t < 4; t++) {
        int c = c0 + t;
        float w;
        if (n < 1024)      w = Wg[(size_t)c * DV + n];
        else if (n < 1536) w = W1[(size_t)c * HH + (n - 1024)];
        else               w = W1[(size_t)(512 + c) * HH + (n - 1536)];
        store_b2(row, c, w);
    }
}
__global__ void k_prep_W1ct(const float* __restrict__ W1) {
    int n = blockIdx.x;
    int c0 = threadIdx.x * 4;
    __half* row = g_W1ct + (size_t)n * 512;
    #pragma unroll
    for (int t = 0; t < 4; t++) {
        int c = c0 + t;
        row[c] = __float2half_rn(W1[(size_t)(1024 + c) * HH + n]);
    }
}
__global__ void k_prep_W2t(const float* __restrict__ W2) {
    int n = blockIdx.x;
    int c0 = threadIdx.x * 4;
    __half* row = g_W2t + (size_t)n * 512;
    #pragma unroll
    for (int t = 0; t < 4; t++) {
        int c = c0 + t;
        row[c] = __float2half_rn(W2[(size_t)c * HH + n]);
    }
}

// =============================================================
// HMMA GEMM, split precision.
// BM=128, BN=256, base-chunk K=64, 512 threads (16 warps, 4x4),
// warp tile 32x64.
// EPI 0 (bf16, 3 terms): A from S (GEMM0), B=g_Ball (hi|lo), C -> g_GUV
// EPI 1 (fp16, 1 term): A = fp16(S_i ⊙ S_j), B=g_W1ct;
//        epi: +U+V+b1, relu -> g_H1 fp16
// EPI 2 (fp16, 1 term): A = g_H1, B=g_W2t;
//        epi: relu(+b2)·W3 row-reduce -> g_tpart
// =============================================================
#define ARS 72                         // smem row stride in 2B elems (144 B)
#define ATILE (128 * ARS * 2)          // 18432 (one 128x64 tile)
#define BTILE (256 * ARS * 2)          // 36864 (one 256x64 tile)
#define AHI(s) ((uint32_t)((s) * 2 * ATILE))
#define ALO(s) ((uint32_t)((s) * 2 * ATILE + ATILE))
#define BOFFN(i) ((uint32_t)(4 * ATILE + (i) * BTILE))
#define SPART    ((uint32_t)(4 * ATILE + 4 * BTILE))    // 221184
#define SMEM_TOT (4 * ATILE + 4 * BTILE + 512)          // 221696

template<int EPI>
__global__ __launch_bounds__(512, 1)
void k_gemm_mma(const float* __restrict__ S,
                const float* __restrict__ bias,
                const float* __restrict__ W3)
{
    extern __shared__ char smem[];
    const uint32_t sb = s2u(smem);
    const int tid = threadIdx.x;
    const int m0 = blockIdx.y * 128;
    const int n0 = blockIdx.x * 256;

    // ---- A loader: thread t -> rows rA0 = t>>3 and rA0+64, k-cols (t&7)*8..+7
    const int rA0 = tid >> 3;
    const int rA1 = rA0 + 64;
    const int kcA = (tid & 7) * 8;
    const float *p0a = nullptr, *p0b = nullptr, *p1a = nullptr, *p1b = nullptr;
    size_t rowOff0 = 0, rowOff1 = 0;
    {
        const int row0 = m0 + rA0, row1 = m0 + rA1;
        if (EPI == 0) {
            p0a = S + (size_t)row0 * DS;
            p1a = S + (size_t)row1 * DS;
        } else if (EPI == 1) {
            int b0_ = row0 / NP, q0 = row0 - b0_ * NP;
            int b1_ = row1 / NP, q1 = row1 - b1_ * NP;
            p0a = S + (size_t)(b0_ * NN + g_iu[q0]) * DS;
            p0b = S + (size_t)(b0_ * NN + g_ju[q0]) * DS;
            p1a = S + (size_t)(b1_ * NN + g_iu[q1]) * DS;
            p1b = S + (size_t)(b1_ * NN + g_ju[q1]) * DS;
        } else {
            rowOff0 = (size_t)row0 * HH;
            rowOff1 = (size_t)row1 * HH;
        }
    }
    const uint32_t aDst0 = (uint32_t)(rA0 * (ARS * 2) + kcA * 2);
    const uint32_t aDst1 = (uint32_t)(rA1 * (ARS * 2) + kcA * 2);

    // Fill A tile(s) for base chunk bc into buffer s.
    // EPI0: bf16 hi+lo tiles.  EPI1: fp16 product (hi only).  EPI2: fp16 H1 copy.
    auto fillA = [&](int bc, int s) {
        const int kk = bc * 64 + kcA;
        if (EPI == 2) {
            *(uint4*)(smem + AHI(s) + aDst0) = *(const uint4*)(g_H1 + rowOff0 + kk);
            *(uint4*)(smem + AHI(s) + aDst1) = *(const uint4*)(g_H1 + rowOff1 + kk);
        } else {
            float4 x0 = *(const float4*)(p0a + kk);
            float4 x1 = *(const float4*)(p0a + kk + 4);
            float f0 = x0.x, f1 = x0.y, f2 = x0.z, f3 = x0.w;
            float f4 = x1.x, f5 = x1.y, f6 = x1.z, f7 = x1.w;
            if (EPI == 1) {
                float4 y0 = *(const float4*)(p0b + kk);
                float4 y1 = *(const float4*)(p0b + kk + 4);
                f0 *= y0.x; f1 *= y0.y; f2 *= y0.z; f3 *= y0.w;
                f4 *= y1.x; f5 *= y1.y; f6 *= y1.z; f7 *= y1.w;
            }
            float4 z0 = *(const float4*)(p1a + kk);
            float4 z1 = *(const float4*)(p1a + kk + 4);
            float g0 = z0.x, g1 = z0.y, g2 = z0.z, g3 = z0.w;
            float g4 = z1.x, g5 = z1.y, g6 = z1.z, g7 = z1.w;
            if (EPI == 1) {
                float4 w0 = *(const float4*)(p1b + kk);
                float4 w1 = *(const float4*)(p1b + kk + 4);
                g0 *= w0.x; g1 *= w0.y; g2 *= w0.z; g3 *= w0.w;
                g4 *= w1.x; g5 *= w1.y; g6 *= w1.z; g7 *= w1.w;
            }
            if (EPI == 0) {
                uint4 vh, vl, uh, ul;
                pack2(f0, f1, vh.x, vl.x); pack2(f2, f3, vh.y, vl.y);
                pack2(f4, f5, vh.z, vl.z); pack2(f6, f7, vh.w, vl.w);
                pack2(g0, g1, uh.x, ul.x); pack2(g2, g3, uh.y, ul.y);
                pack2(g4, g5, uh.z, ul.z); pack2(g6, g7, uh.w, ul.w);
                *(uint4*)(smem + AHI(s) + aDst0) = vh;
                *(uint4*)(smem + ALO(s) + aDst0) = vl;
                *(uint4*)(smem + AHI(s) + aDst1) = uh;
                *(uint4*)(smem + ALO(s) + aDst1) = ul;
            } else {
                uint4 vh, uh;
                vh.x = packh(f0, f1); vh.y = packh(f2, f3);
                vh.z = packh(f4, f5); vh.w = packh(f6, f7);
                uh.x = packh(g0, g1); uh.y = packh(g2, g3);
                uh.z = packh(g4, g5); uh.w = packh(g6, g7);
                *(uint4*)(smem + AHI(s) + aDst0) = vh;
                *(uint4*)(smem + AHI(s) + aDst1) = uh;
            }
        }
    };
    // EPI0: colbase 0=hi block / 512=lo block out of 1024-col bf16 array
    auto fillB0 = [&](int colbase, int bc, int buf) {
        #pragma unroll
        for (int rep = 0; rep < 4; rep++) {
            int gg = tid + rep * 512;
            int rb = gg >> 3, cb = (gg & 7) * 8;
            uint32_t dst = sb + BOFFN(buf) + (uint32_t)(rb * (ARS * 2) + cb * 2);
            const __nv_bfloat16* src = g_Ball + (size_t)(n0 + rb) * 1024 + colbase + bc * 64 + cb;
            CPASYNC16(dst, src);
        }
        CPCOMMIT();
    };
    // EPI1/2: 512-col fp16 weight array
    const __half* __restrict__ Bh = (EPI == 1) ? g_W1ct : g_W2t;
    auto fillBh = [&](int bc, int buf) {
        #pragma unroll
        for (int rep = 0; rep < 4; rep++) {
            int gg = tid + rep * 512;
            int rb = gg >> 3, cb = (gg & 7) * 8;
            uint32_t dst = sb + BOFFN(buf) + (uint32_t)(rb * (ARS * 2) + cb * 2);
            const __half* src = Bh + (size_t)(n0 + rb) * 512 + bc * 64 + cb;
            CPASYNC16(dst, src);
        }
        CPCOMMIT();
    };

    // ---- warp layout
    const int wid = tid >> 5;
    const int wm = wid >> 2;     // rows: wm*32
    const int wn = wid & 3;      // cols: wn*64
    const int l = tid & 31;

    float acc[2][8][4];
    #pragma unroll
    for (int mi = 0; mi < 2; mi++)
        #pragma unroll
        for (int nb = 0; nb < 8; nb++)
            #pragma unroll
            for (int q = 0; q < 4; q++) acc[mi][nb][q] = 0.f;

    if (EPI == 2) {
        if (tid < 128) *(float*)(smem + SPART + tid * 4) = 0.f;
    }

    const uint32_t lrow = (uint32_t)(l & 15);
    const uint32_t lcol8 = (uint32_t)((l >> 4) * 8);

    if (EPI == 0) {
        // ======== bf16 3-term mainloop ========
        fillB0(0,   0, 0);
        fillB0(512, 0, 1);
        fillB0(0,   1, 2);
        fillB0(512, 1, 3);
        fillA(0, 0);

        for (int bc = 0; bc < NBC; bc++) {
            const int ab = bc & 1;
            const int bhi = (2 * bc) & 3;
            const int blo = (2 * bc + 1) & 3;
            if (bc + 1 < NBC) fillA(bc + 1, ab ^ 1);
            if (bc < NBC - 1) { CPWAIT2(); } else { CPWAIT0(); }
            __syncthreads();

            const uint32_t ahibase = sb + AHI(ab);
            const uint32_t alobase = sb + ALO(ab);
            const uint32_t bhibase = sb + BOFFN(bhi);
            const uint32_t blobase = sb + BOFFN(blo);
            #pragma unroll
            for (int ks = 0; ks < 4; ks++) {
                const uint32_t arow = ((uint32_t)(wm * 32) + lrow) * (ARS * 2)
                                    + ((uint32_t)(ks * 16) + lcol8) * 2;
                const uint32_t brow = ((uint32_t)(wn * 64) + lrow) * (ARS * 2)
                                    + ((uint32_t)(ks * 16) + lcol8) * 2;
                uint32_t ah[2][4], al[2][4], bf[4][4];
                #pragma unroll
                for (int mi = 0; mi < 2; mi++) {
                    ldsm_x4(ah[mi], ahibase + arow + (uint32_t)(mi * 16 * ARS * 2));
                    ldsm_x4(al[mi], alobase + arow + (uint32_t)(mi * 16 * ARS * 2));
                }
                #pragma unroll
                for (int np = 0; np < 4; np++)
                    ldsm_x4(bf[np], bhibase + brow + (uint32_t)(np * 16 * ARS * 2));
                #pragma unroll
                for (int mi = 0; mi < 2; mi++)
                    #pragma unroll
                    for (int nb = 0; nb < 8; nb++) {
                        int np = nb >> 1, hf = nb & 1;
                        mma16816(acc[mi][nb], ah[mi], bf[np][hf], bf[np][2 + hf]);
                        mma16816(acc[mi][nb], al[mi], bf[np][hf], bf[np][2 + hf]);
                    }
                #pragma unroll
                for (int np = 0; np < 4; np++)
                    ldsm_x4(bf[np], blobase + brow + (uint32_t)(np * 16 * ARS * 2));
                #pragma unroll
                for (int mi = 0; mi < 2; mi++)
                    #pragma unroll
                    for (int nb = 0; nb < 8; nb++) {
                        int np = nb >> 1, hf = nb & 1;
                        mma16816(acc[mi][nb], ah[mi], bf[np][hf], bf[np][2 + hf]);
                    }
            }
            __syncthreads();
            if (bc + 2 < NBC) { fillB0(0, bc + 2, bhi); fillB0(512, bc + 2, blo); }
        }
    } else {
        // ======== fp16 single-term mainloop ========
        fillBh(0, 0); fillBh(1, 1); fillBh(2, 2); fillBh(3, 3);
        fillA(0, 0);

        for (int bc = 0; bc < NBC; bc++) {
            const int ab = bc & 1;
            const int bb = bc & 3;
            if (bc + 1 < NBC) fillA(bc + 1, ab ^ 1);
            if (bc <= NBC - 4)      { CPWAIT3(); }
            else if (bc == NBC - 3) { CPWAIT2(); }
            else if (bc == NBC - 2) { CPWAIT1(); }
            else                    { CPWAIT0(); }
            __syncthreads();

            const uint32_t ahibase = sb + AHI(ab);
            const uint32_t bbase   = sb + BOFFN(bb);
            #pragma unroll
            for (int ks = 0; ks < 4; ks++) {
                const uint32_t arow = ((uint32_t)(wm * 32) + lrow) * (ARS * 2)
                                    + ((uint32_t)(ks * 16) + lcol8) * 2;
                const uint32_t brow = ((uint32_t)(wn * 64) + lrow) * (ARS * 2)
                                    + ((uint32_t)(ks * 16) + lcol8) * 2;
                uint32_t ah[2][4], bf[4][4];
                #pragma unroll
                for (int mi = 0; mi < 2; mi++)
                    ldsm_x4(ah[mi], ahibase + arow + (uint32_t)(mi * 16 * ARS * 2));
                #pragma unroll
                for (int np = 0; np < 4; np++)
                    ldsm_x4(bf[np], bbase + brow + (uint32_t)(np * 16 * ARS * 2));
                #pragma unroll
                for (int mi = 0; mi < 2; mi++)
                    #pragma unroll
                    for (int nb = 0; nb < 8; nb++) {
                        int np = nb >> 1, hf = nb & 1;
                        mma16816h(acc[mi][nb], ah[mi], bf[np][hf], bf[np][2 + hf]);
                    }
            }
            __syncthreads();
            if (bc + 4 < NBC) fillBh(bc + 4, bb);
        }
    }

    // ---- epilogue (register accumulators) ----
    float rsum[2][2] = {{0.f, 0.f}, {0.f, 0.f}};
    #pragma unroll
    for (int mi = 0; mi < 2; mi++) {
        const int rl = wm * 32 + mi * 16 + (l >> 2);
        const int row0 = m0 + rl;
        const int row1 = row0 + 8;
        const float *U0 = nullptr, *V0 = nullptr, *U1 = nullptr, *V1 = nullptr;
        if (EPI == 1) {
            int b0_ = row0 / NP, p0_ = row0 - b0_ * NP;
            int b1_ = row1 / NP, p1_ = row1 - b1_ * NP;
            U0 = g_GUV + (size_t)(b0_ * NN + g_iu[p0_]) * 2048 + 1024;
            V0 = g_GUV + (size_t)(b0_ * NN + g_ju[p0_]) * 2048 + 1536;
            U1 = g_GUV + (size_t)(b1_ * NN + g_iu[p1_]) * 2048 + 1024;
            V1 = g_GUV + (size_t)(b1_ * NN + g_ju[p1_]) * 2048 + 1536;
        }
        #pragma unroll
        for (int nb = 0; nb < 8; nb++) {
            const int col = n0 + wn * 64 + nb * 8 + (l & 3) * 2;
            float c0 = acc[mi][nb][0], c1 = acc[mi][nb][1];
            float c2 = acc[mi][nb][2], c3 = acc[mi][nb][3];
            if (EPI == 0) {
                float2 u = {c0, c1}, v = {c2, c3};
                *(float2*)&g_GUV[(size_t)row0 * 2048 + col] = u;
                *(float2*)&g_GUV[(size_t)row1 * 2048 + col] = v;
            } else if (EPI == 1) {
                float v0 = fmaxf(c0 + U0[col]     + V0[col]     + bias[col],     0.f);
                float v1 = fmaxf(c1 + U0[col + 1] + V0[col + 1] + bias[col + 1], 0.f);
                float v2 = fmaxf(c2 + U1[col]     + V1[col]     + bias[col],     0.f);
                float v3 = fmaxf(c3 + U1[col + 1] + V1[col + 1] + bias[col + 1], 0.f);
                *(uint32_t*)&g_H1[(size_t)row0 * HH + col] = packh(v0, v1);
                *(uint32_t*)&g_H1[(size_t)row1 * HH + col] = packh(v2, v3);
            } else {
                float w0 = W3[col], w1 = W3[col + 1];
                float bb0 = bias[col], bb1 = bias[col + 1];
                rsum[mi][0] += fmaxf(c0 + bb0, 0.f) * w0 + fmaxf(c1 + bb1, 0.f) * w1;
                rsum[mi][1] += fmaxf(c2 + bb0, 0.f) * w0 + fmaxf(c3 + bb1, 0.f) * w1;
            }
        }
    }
    if (EPI == 2) {
        __syncthreads();
        #pragma unroll
        for (int mi = 0; mi < 2; mi++) {
            #pragma unroll
            for (int q = 0; q < 2; q++) {
                float v = rsum[mi][q];
                v += __shfl_xor_sync(0xffffffffu, v, 1);
                v += __shfl_xor_sync(0xffffffffu, v, 2);
                if ((l & 3) == 0) {
                    int rl = wm * 32 + mi * 16 + (l >> 2) + q * 8;
                    atomicAdd((float*)(smem + SPART + rl * 4), v);
                }
            }
        }
        __syncthreads();
        if (tid < 128)
            g_tpart[(size_t)blockIdx.x * BPROWS + m0 + tid] = *(float*)(smem + SPART + tid * 4);
    }
}

// =============================================================
// Post-GEMM small kernels
// =============================================================
__global__ __launch_bounds__(256) void k_M(const float* __restrict__ I,
                                           float* __restrict__ out)
{
    __shared__ float Gs[32][65];
    __shared__ float Is[40][65];
    const int b = blockIdx.x;
    const int tid = threadIdx.x;
    const int n = tid >> 3;
    const int lg = tid & 7;
    float acc[5] = {0.f, 0.f, 0.f, 0.f, 0.f};

    for (int kt = 0; kt < DV; kt += 64) {
        __syncthreads();
        for (int t = tid; t < 32 * 64; t += 256) {
            int r = t >> 6, c = t & 63;
            Gs[r][c] = g_GUV[(size_t)(b * NN + r) * 2048 + kt + c];
        }
        for (int t = tid; t < 40 * 64; t += 256) {
            int r = t >> 6, c = t & 63;
            Is[r][c] = (r < NLW) ? I[(size_t)b * NLW * DV + (size_t)r * DV + kt + c] : 0.f;
        }
        __syncthreads();
        #pragma unroll 4
        for (int c = 0; c < 64; c++) {
            float g = Gs[n][c];
            #pragma unroll
            for (int s = 0; s < 5; s++)
                acc[s] = fmaf(g, Is[lg + 8 * s][c], acc[s]);
        }
    }
    #pragma unroll
    for (int s = 0; s < 5; s++) {
        int l = lg + 8 * s;
        if (l < NLW) {
            float v = acc[s];
            g_M[b * NNL + n * NLW + l] = v;
            out[1 + b * NNL + n * NLW + l] = v;
        }
    }
}

__global__ void k_A(const float* __restrict__ sm, const float* __restrict__ im)
{
    const int b = blockIdx.x, t = threadIdx.x;
    __shared__ float red[64];
    __shared__ float sms[32];
    if (t < 32) sms[t] = sm[b * NN + t];
    __syncthreads();
    float msum = 0.f;
    for (int o = t; o < NNL; o += 64) msum += g_M[b * NNL + o];
    red[t] = msum;
    if (t < NLW) {
        float a = 0.f;
        #pragma unroll
        for (int n = 0; n < NN; n++)
            a = fmaf(g_M[b * NNL + n * NLW + t], sms[n], a);
        g_Avec[b * NLW + t] = a;
    }
    __syncthreads();
    for (int s = 32; s > 0; s >>= 1) {
        if (t < s) red[t] += red[t + s];
        __syncthreads();
    }
    if (t == 0) {
        g_Msum[b] = red[0];
        float cs = 0.f, ci = 0.f;
        for (int n = 0; n < NN; n++) cs += sms[n];
        for (int l = 0; l < NLW; l++) ci += im[b * NLW + l];
        g_cs[b] = cs;
        g_ci[b] = ci;
    }
}

__global__ void k_sent(const float* __restrict__ im)
{
    const int i = blockIdx.x, j = threadIdx.x;
    __shared__ float As[NLW];
    __shared__ float csI, msI;
    if (j < NLW) As[j] = g_Avec[i * NLW + j];
    if (j == 0) { csI = g_cs[i]; msI = g_Msum[i]; }
    __syncthreads();
    float d = 0.f;
    #pragma unroll
    for (int l = 0; l < NLW; l++) d = fmaf(As[l], im[j * NLW + l], d);
    float cnt = csI * g_ci[j];
    g_sent[i * NB + j] = (cnt > 0.f) ? (d / cnt) : (msI / (float)NNL);
}

__global__ void k_loss(float* __restrict__ out)
{
    const int t = threadIdx.x;
    float mx = -1e30f;
    for (int j = 0; j < NB; j++) mx = fmaxf(mx, g_sent[t * NB + j]);
    float se = 0.f, rs = 0.f;
    for (int j = 0; j < NB; j++) {
        float v = g_sent[t * NB + j];
        se += expf(v - mx);
        rs += v;
    }
    float lr = mx + logf(se);
    float mx2 = -1e30f;
    for (int i = 0; i < NB; i++) mx2 = fmaxf(mx2, g_sent[i * NB + t]);
    float se2 = 0.f;
    for (int i = 0; i < NB; i++) se2 += expf(g_sent[i * NB + t] - mx2);
    float lc = mx2 + logf(se2);
    __shared__ float r1[128], r2[128], r3[128];
    r1[t] = lr; r2[t] = lc; r3[t] = rs;
    __syncthreads();
    for (int s = 64; s > 0; s >>= 1) {
        if (t < s) { r1[t] += r1[t + s]; r2[t] += r2[t + s]; r3[t] += r3[t + s]; }
        __syncthreads();
    }
    if (t == 0) out[0] = r1[0] + r2[0] - 2.f * r3[0] / (float)NB;
}

__global__ void k_text_final(const float* __restrict__ b3, float* __restrict__ out)
{
    int m = blockIdx.x * 256 + threadIdx.x;
    if (m >= BPROWS) return;
    out[1 + NB * NNL + m] = b3[0] + g_tpart[m] + g_tpart[(size_t)BPROWS + m];
}

// =============================================================
extern "C" void kernel_launch(void* const* d_in, const int* in_sizes, int n_in,
                              void* d_out, int out_size)
{
    const float* S   = (const float*)d_in[0];
    const float* I   = (const float*)d_in[1];
    const float* sm  = (const float*)d_in[2];
    const float* im  = (const float*)d_in[3];
    const float* Wg  = (const float*)d_in[4];
    const float* W1  = (const float*)d_in[5];
    const float* b1  = (const float*)d_in[6];
    const float* W2  = (const float*)d_in[7];
    const float* b2  = (const float*)d_in[8];
    const float* W3  = (const float*)d_in[9];
    const float* b3  = (const float*)d_in[10];
    float* out = (float*)d_out;

    cudaFuncSetAttribute(k_gemm_mma<0>, cudaFuncAttributeMaxDynamicSharedMemorySize, SMEM_TOT);
    cudaFuncSetAttribute(k_gemm_mma<1>, cudaFuncAttributeMaxDynamicSharedMemorySize, SMEM_TOT);
    cudaFuncSetAttribute(k_gemm_mma<2>, cudaFuncAttributeMaxDynamicSharedMemorySize, SMEM_TOT);

    // preps
    k_init_pairs<<<1, 512>>>();
    k_prep_Ball<<<2048, 128>>>(Wg, W1);
    k_prep_W1ct<<<512, 128>>>(W1);
    k_prep_W2t<<<512, 128>>>(W2);

    // GEMM0: [G|U|V] = S @ [Wg | W1a | W1b]   (M=4096, N=2048, bf16 3-term)
    k_gemm_mma<0><<<dim3(2048 / 256, BNROWS / 128), 512, SMEM_TOT>>>(S, nullptr, nullptr);

    // image-grounding tail
    k_M<<<NB, 256>>>(I, out);
    k_A<<<NB, 64>>>(sm, im);
    k_sent<<<NB, NB>>>(im);
    k_loss<<<1, NB>>>(out);

    // text path (fp16 single-term)
    k_gemm_mma<1><<<dim3(HH / 256, BPROWS / 128), 512, SMEM_TOT>>>(S, b1, nullptr);
    k_gemm_mma<2><<<dim3(HH / 256, BPROWS / 128), 512, SMEM_TOT>>>(nullptr, b2, W3);
    k_text_final<<<(BPROWS + 255) / 256, 256>>>(b3, out);
}

// round 16
// speedup vs baseline: 1.5332x; 1.5332x over previous
#include <cuda_runtime.h>
#include <cuda_bf16.h>
#include <cuda_fp16.h>
#include <cstdint>
#include <stdint.h>
#include <math.h>

// Problem constants
#define NB 128
#define NN 32
#define NLW 36
#define DS 512
#define DV 1024
#define HH 512
#define NP 496
#define NNL (NN*NLW)      // 1152
#define BNROWS (NB*NN)    // 4096
#define BPROWS (NB*NP)    // 63488
#define NBC 8              // base chunks of 64 over K=512

// ---- scratch (__device__ globals; no runtime allocation) ----
__device__ __nv_bfloat16 g_Ball[(size_t)2048 * 1024];   // [Wg^T;W1a^T;W1b^T] (hi|lo) bf16
__device__ __nv_bfloat16 g_S2 [(size_t)BNROWS * 1024];  // S (hi|lo) bf16
__device__ __half g_W1ct[(size_t)HH * 512];             // W1c^T fp16
__device__ __half g_W2t [(size_t)HH * 512];             // W2^T  fp16
__device__ __half g_Pf  [(size_t)BPROWS * HH];          // pair products fp16
__device__ __half g_H1  [(size_t)BPROWS * HH];          // H1 fp16
__device__ float g_GUV[(size_t)BNROWS * 2048];          // [G | U | V] fp32
__device__ float g_tpart[(size_t)2 * BPROWS];
__device__ float g_M[NB * NNL];
__device__ float g_Avec[NB * NLW];
__device__ float g_cs[NB];
__device__ float g_ci[NB];
__device__ float g_Msum[NB];
__device__ float g_sent[NB * NB];
__device__ int   g_iu[NP];
__device__ int   g_ju[NP];

// =============================================================
// helpers
// =============================================================
__device__ __forceinline__ uint32_t s2u(const void* p) {
    uint32_t a;
    asm("{ .reg .u64 t; cvta.to.shared.u64 t, %1; cvt.u32.u64 %0, t; }" : "=r"(a) : "l"(p));
    return a;
}
__device__ __forceinline__ void ldsm_x4(uint32_t* r, uint32_t addr) {
    asm volatile("ldmatrix.sync.aligned.m8n8.x4.shared.b16 {%0,%1,%2,%3}, [%4];"
        : "=r"(r[0]), "=r"(r[1]), "=r"(r[2]), "=r"(r[3]) : "r"(addr));
}
__device__ __forceinline__ void mma16816(float* c, const uint32_t* a, uint32_t b0, uint32_t b1) {
    asm volatile(
        "mma.sync.aligned.m16n8k16.row.col.f32.bf16.bf16.f32 "
        "{%0,%1,%2,%3}, {%4,%5,%6,%7}, {%8,%9}, {%0,%1,%2,%3};"
        : "+f"(c[0]), "+f"(c[1]), "+f"(c[2]), "+f"(c[3])
        : "r"(a[0]), "r"(a[1]), "r"(a[2]), "r"(a[3]), "r"(b0), "r"(b1));
}
__device__ __forceinline__ void mma16816h(float* c, const uint32_t* a, uint32_t b0, uint32_t b1) {
    asm volatile(
        "mma.sync.aligned.m16n8k16.row.col.f32.f16.f16.f32 "
        "{%0,%1,%2,%3}, {%4,%5,%6,%7}, {%8,%9}, {%0,%1,%2,%3};"
        : "+f"(c[0]), "+f"(c[1]), "+f"(c[2]), "+f"(c[3])
        : "r"(a[0]), "r"(a[1]), "r"(a[2]), "r"(a[3]), "r"(b0), "r"(b1));
}
#define CPASYNC16(dst, src) asm volatile("cp.async.cg.shared.global [%0], [%1], 16;" :: "r"(dst), "l"(src))
#define CPCOMMIT()          asm volatile("cp.async.commit_group;" ::: "memory")
#define CPWAIT1()           asm volatile("cp.async.wait_group 1;" ::: "memory")
#define CPWAIT0()           asm volatile("cp.async.wait_group 0;" ::: "memory")

__device__ __forceinline__ void split2(float v, __nv_bfloat16& h, __nv_bfloat16& l) {
    h = __float2bfloat16(v);
    l = __float2bfloat16(v - __bfloat162float(h));
}
__device__ __forceinline__ uint32_t packh(float a, float b) {
    __half2 h = __halves2half2(__float2half_rn(a), __float2half_rn(b));
    return *(uint32_t*)&h;
}
__device__ __forceinline__ uint32_t packbf(__nv_bfloat16 a, __nv_bfloat16 b) {
    __nv_bfloat162 h = __halves2bfloat162(a, b);
    return *(uint32_t*)&h;
}

// =============================================================
// Prep kernels
// =============================================================
__global__ void k_init_pairs() {
    int p = threadIdx.x;
    if (p >= NP) return;
    int cum = 0;
    for (int i = 0; i < NN; i++) {
        int cnt = NN - 1 - i;
        if (p < cum + cnt) { g_iu[p] = i; g_ju[p] = i + 1 + (p - cum); return; }
        cum += cnt;
    }
}
// B layout per row (1024 cols, bf16): [0,512)=hi, [512,1024)=lo
__device__ __forceinline__ void store_b2(__nv_bfloat16* row, int c, float v) {
    __nv_bfloat16 h, l; split2(v, h, l);
    row[c] = h; row[512 + c] = l;
}
__global__ void k_prep_Ball(const float* __restrict__ Wg, const float* __restrict__ W1) {
    int n = blockIdx.x;                 // 2048
    int c0 = threadIdx.x * 4;           // 128 thr
    __nv_bfloat16* row = g_Ball + (size_t)n * 1024;
    #pragma unroll
    for (int t = 0; t < 4; t++) {
        int c = c0 + t;
        float w;
        if (n < 1024)      w = Wg[(size_t)c * DV + n];
        else if (n < 1536) w = W1[(size_t)c * HH + (n - 1024)];
        else               w = W1[(size_t)(512 + c) * HH + (n - 1536)];
        store_b2(row, c, w);
    }
}
__global__ void k_prep_W1ct(const float* __restrict__ W1) {
    int n = blockIdx.x;
    int c0 = threadIdx.x * 4;
    __half* row = g_W1ct + (size_t)n * 512;
    #pragma unroll
    for (int t = 0; t < 4; t++) {
        int c = c0 + t;
        row[c] = __float2half_rn(W1[(size_t)(1024 + c) * HH + n]);
    }
}
__global__ void k_prep_W2t(const float* __restrict__ W2) {
    int n = blockIdx.x;
    int c0 = threadIdx.x * 4;
    __half* row = g_W2t + (size_t)n * 512;
    #pragma unroll
    for (int t = 0; t < 4; t++) {
        int c = c0 + t;
        row[c] = __float2half_rn(W2[(size_t)c * HH + n]);
    }
}
// S -> bf16 hi|lo (A operand of GEMM0)
__global__ void k_prep_S2(const float* __restrict__ S) {
    int r = blockIdx.x;                 // 4096
    int c = threadIdx.x * 4;            // 128 thr
    float4 v = *(const float4*)(S + (size_t)r * DS + c);
    __nv_bfloat16 h0, l0, h1, l1, h2, l2, h3, l3;
    split2(v.x, h0, l0); split2(v.y, h1, l1);
    split2(v.z, h2, l2); split2(v.w, h3, l3);
    uint2 hw, lw;
    hw.x = packbf(h0, h1); hw.y = packbf(h2, h3);
    lw.x = packbf(l0, l1); lw.y = packbf(l2, l3);
    *(uint2*)(g_S2 + (size_t)r * 1024 + c)       = hw;
    *(uint2*)(g_S2 + (size_t)r * 1024 + 512 + c) = lw;
}
// pair products -> fp16 (A operand of GEMM1)
__global__ void k_prep_Pf(const float* __restrict__ S) {
    int m = blockIdx.x;                 // 63488
    int b = m / NP, p = m - b * NP;
    const float* Si = S + (size_t)(b * NN + g_iu[p]) * DS;
    const float* Sj = S + (size_t)(b * NN + g_ju[p]) * DS;
    int c = threadIdx.x * 4;            // 128 thr
    float4 a = *(const float4*)(Si + c);
    float4 d = *(const float4*)(Sj + c);
    uint2 w;
    w.x = packh(a.x * d.x, a.y * d.y);
    w.y = packh(a.z * d.z, a.w * d.w);
    *(uint2*)(g_Pf + (size_t)m * HH + c) = w;
}

// =============================================================
// HMMA GEMM — all operands prematerialized, A and B via cp.async.
// BM=128, BN=256, chunk K=64, 512 threads (16 warps, 4x4), warp tile 32x64.
// EPI 0 (bf16, 3 terms): A=g_S2(hi|lo), B=g_Ball(hi|lo) -> g_GUV fp32
// EPI 1 (fp16, 1 term):  A=g_Pf, B=g_W1ct; epi: +U+V+b1, relu -> g_H1
// EPI 2 (fp16, 1 term):  A=g_H1, B=g_W2t;  epi: relu(+b2)·W3 -> g_tpart
// =============================================================
#define ARS 72                         // smem row stride in 2B elems (144 B)
#define ATILE (128 * ARS * 2)          // 18432
#define BTILE (256 * ARS * 2)          // 36864
#define AHI(s) ((uint32_t)((s) * 2 * ATILE))
#define ALO(s) ((uint32_t)((s) * 2 * ATILE + ATILE))
#define BOFFN(i) ((uint32_t)(4 * ATILE + (i) * BTILE))
#define SPART    ((uint32_t)(4 * ATILE + 4 * BTILE))    // 221184
#define SMEM_TOT (4 * ATILE + 4 * BTILE + 512)          // 221696

template<int EPI>
__global__ __launch_bounds__(512, 1)
void k_gemm_mma(const float* __restrict__ bias, const float* __restrict__ W3)
{
    extern __shared__ char smem[];
    const uint32_t sb = s2u(smem);
    const int tid = threadIdx.x;
    const int m0 = blockIdx.y * 128;
    const int n0 = blockIdx.x * 256;

    // ---- async A loader: thread t -> rows rA0=t>>3, rA0+64; k-cols (t&7)*8
    const int rA0 = tid >> 3;
    const int rA1 = rA0 + 64;
    const int kcA = (tid & 7) * 8;
    const uint32_t aDst0 = (uint32_t)(rA0 * (ARS * 2) + kcA * 2);
    const uint32_t aDst1 = (uint32_t)(rA1 * (ARS * 2) + kcA * 2);

    auto fillA = [&](int bc, int s) {
        if (EPI == 0) {
            const __nv_bfloat16* s0 = g_S2 + (size_t)(m0 + rA0) * 1024 + bc * 64 + kcA;
            const __nv_bfloat16* s1 = g_S2 + (size_t)(m0 + rA1) * 1024 + bc * 64 + kcA;
            CPASYNC16(sb + AHI(s) + aDst0, s0);
            CPASYNC16(sb + AHI(s) + aDst1, s1);
            CPASYNC16(sb + ALO(s) + aDst0, s0 + 512);
            CPASYNC16(sb + ALO(s) + aDst1, s1 + 512);
        } else {
            const __half* base = (EPI == 1) ? g_Pf : g_H1;
            CPASYNC16(sb + AHI(s) + aDst0, base + (size_t)(m0 + rA0) * HH + bc * 64 + kcA);
            CPASYNC16(sb + AHI(s) + aDst1, base + (size_t)(m0 + rA1) * HH + bc * 64 + kcA);
        }
    };
    auto fillB0 = [&](int colbase, int bc, int buf) {
        #pragma unroll
        for (int rep = 0; rep < 4; rep++) {
            int gg = tid + rep * 512;
            int rb = gg >> 3, cb = (gg & 7) * 8;
            uint32_t dst = sb + BOFFN(buf) + (uint32_t)(rb * (ARS * 2) + cb * 2);
            const __nv_bfloat16* src = g_Ball + (size_t)(n0 + rb) * 1024 + colbase + bc * 64 + cb;
            CPASYNC16(dst, src);
        }
    };
    const __half* __restrict__ Bh = (EPI == 1) ? g_W1ct : g_W2t;
    auto fillBh = [&](int bc, int buf) {
        #pragma unroll
        for (int rep = 0; rep < 4; rep++) {
            int gg = tid + rep * 512;
            int rb = gg >> 3, cb = (gg & 7) * 8;
            uint32_t dst = sb + BOFFN(buf) + (uint32_t)(rb * (ARS * 2) + cb * 2);
            const __half* src = Bh + (size_t)(n0 + rb) * 512 + bc * 64 + cb;
            CPASYNC16(dst, src);
        }
    };
    auto issueGroup = [&](int bc, int s) {
        fillA(bc, s);
        if (EPI == 0) { fillB0(0, bc, 2 * s); fillB0(512, bc, 2 * s + 1); }
        else          { fillBh(bc, s); }
        CPCOMMIT();
    };

    // ---- warp layout
    const int wid = tid >> 5;
    const int wm = wid >> 2;
    const int wn = wid & 3;
    const int l = tid & 31;

    float acc[2][8][4];
    #pragma unroll
    for (int mi = 0; mi < 2; mi++)
        #pragma unroll
        for (int nb = 0; nb < 8; nb++)
            #pragma unroll
            for (int q = 0; q < 4; q++) acc[mi][nb][q] = 0.f;

    if (EPI == 2) {
        if (tid < 128) *(float*)(smem + SPART + tid * 4) = 0.f;
    }

    const uint32_t lrow = (uint32_t)(l & 15);
    const uint32_t lcol8 = (uint32_t)((l >> 4) * 8);

    // ---- depth-2 pipeline: groups {A,B} per chunk, double-buffered
    issueGroup(0, 0);
    issueGroup(1, 1);

    for (int bc = 0; bc < NBC; bc++) {
        const int s = bc & 1;
        if (bc < NBC - 1) { CPWAIT1(); } else { CPWAIT0(); }
        __syncthreads();

        const uint32_t ahibase = sb + AHI(s);
        if (EPI == 0) {
            const uint32_t alobase = sb + ALO(s);
            const uint32_t bhibase = sb + BOFFN(2 * s);
            const uint32_t blobase = sb + BOFFN(2 * s + 1);
            #pragma unroll
            for (int ks = 0; ks < 4; ks++) {
                const uint32_t arow = ((uint32_t)(wm * 32) + lrow) * (ARS * 2)
                                    + ((uint32_t)(ks * 16) + lcol8) * 2;
                const uint32_t brow = ((uint32_t)(wn * 64) + lrow) * (ARS * 2)
                                    + ((uint32_t)(ks * 16) + lcol8) * 2;
                uint32_t ah[2][4], al[2][4], bf[4][4];
                #pragma unroll
                for (int mi = 0; mi < 2; mi++) {
                    ldsm_x4(ah[mi], ahibase + arow + (uint32_t)(mi * 16 * ARS * 2));
                    ldsm_x4(al[mi], alobase + arow + (uint32_t)(mi * 16 * ARS * 2));
                }
                #pragma unroll
                for (int np = 0; np < 4; np++)
                    ldsm_x4(bf[np], bhibase + brow + (uint32_t)(np * 16 * ARS * 2));
                #pragma unroll
                for (int mi = 0; mi < 2; mi++)
                    #pragma unroll
                    for (int nb = 0; nb < 8; nb++) {
                        int np = nb >> 1, hf = nb & 1;
                        mma16816(acc[mi][nb], ah[mi], bf[np][hf], bf[np][2 + hf]);
                        mma16816(acc[mi][nb], al[mi], bf[np][hf], bf[np][2 + hf]);
                    }
                #pragma unroll
                for (int np = 0; np < 4; np++)
                    ldsm_x4(bf[np], blobase + brow + (uint32_t)(np * 16 * ARS * 2));
                #pragma unroll
                for (int mi = 0; mi < 2; mi++)
                    #pragma unroll
                    for (int nb = 0; nb < 8; nb++) {
                        int np = nb >> 1, hf = nb & 1;
                        mma16816(acc[mi][nb], ah[mi], bf[np][hf], bf[np][2 + hf]);
                    }
            }
        } else {
            const uint32_t bbase = sb + BOFFN(s);
            #pragma unroll
            for (int ks = 0; ks < 4; ks++) {
                const uint32_t arow = ((uint32_t)(wm * 32) + lrow) * (ARS * 2)
                                    + ((uint32_t)(ks * 16) + lcol8) * 2;
                const uint32_t brow = ((uint32_t)(wn * 64) + lrow) * (ARS * 2)
                                    + ((uint32_t)(ks * 16) + lcol8) * 2;
                uint32_t ah[2][4], bf[4][4];
                #pragma unroll
                for (int mi = 0; mi < 2; mi++)
                    ldsm_x4(ah[mi], ahibase + arow + (uint32_t)(mi * 16 * ARS * 2));
                #pragma unroll
                for (int np = 0; np < 4; np++)
                    ldsm_x4(bf[np], bbase + brow + (uint32_t)(np * 16 * ARS * 2));
                #pragma unroll
                for (int mi = 0; mi < 2; mi++)
                    #pragma unroll
                    for (int nb = 0; nb < 8; nb++) {
                        int np = nb >> 1, hf = nb & 1;
                        mma16816h(acc[mi][nb], ah[mi], bf[np][hf], bf[np][2 + hf]);
                    }
            }
        }
        __syncthreads();
        if (bc + 2 < NBC) issueGroup(bc + 2, s);
    }

    // ---- epilogue (register accumulators) ----
    float rsum[2][2] = {{0.f, 0.f}, {0.f, 0.f}};
    #pragma unroll
    for (int mi = 0; mi < 2; mi++) {
        const int rl = wm * 32 + mi * 16 + (l >> 2);
        const int row0 = m0 + rl;
        const int row1 = row0 + 8;
        const float *U0 = nullptr, *V0 = nullptr, *U1 = nullptr, *V1 = nullptr;
        if (EPI == 1) {
            int b0_ = row0 / NP, p0_ = row0 - b0_ * NP;
            int b1_ = row1 / NP, p1_ = row1 - b1_ * NP;
            U0 = g_GUV + (size_t)(b0_ * NN + g_iu[p0_]) * 2048 + 1024;
            V0 = g_GUV + (size_t)(b0_ * NN + g_ju[p0_]) * 2048 + 1536;
            U1 = g_GUV + (size_t)(b1_ * NN + g_iu[p1_]) * 2048 + 1024;
            V1 = g_GUV + (size_t)(b1_ * NN + g_ju[p1_]) * 2048 + 1536;
        }
        #pragma unroll
        for (int nb = 0; nb < 8; nb++) {
            const int col = n0 + wn * 64 + nb * 8 + (l & 3) * 2;
            float c0 = acc[mi][nb][0], c1 = acc[mi][nb][1];
            float c2 = acc[mi][nb][2], c3 = acc[mi][nb][3];
            if (EPI == 0) {
                float2 u = {c0, c1}, v = {c2, c3};
                *(float2*)&g_GUV[(size_t)row0 * 2048 + col] = u;
                *(float2*)&g_GUV[(size_t)row1 * 2048 + col] = v;
            } else if (EPI == 1) {
                float v0 = fmaxf(c0 + U0[col]     + V0[col]     + bias[col],     0.f);
                float v1 = fmaxf(c1 + U0[col + 1] + V0[col + 1] + bias[col + 1], 0.f);
                float v2 = fmaxf(c2 + U1[col]     + V1[col]     + bias[col],     0.f);
                float v3 = fmaxf(c3 + U1[col + 1] + V1[col + 1] + bias[col + 1], 0.f);
                *(uint32_t*)&g_H1[(size_t)row0 * HH + col] = packh(v0, v1);
                *(uint32_t*)&g_H1[(size_t)row1 * HH + col] = packh(v2, v3);
            } else {
                float w0 = W3[col], w1 = W3[col + 1];
                float bb0 = bias[col], bb1 = bias[col + 1];
                rsum[mi][0] += fmaxf(c0 + bb0, 0.f) * w0 + fmaxf(c1 + bb1, 0.f) * w1;
                rsum[mi][1] += fmaxf(c2 + bb0, 0.f) * w0 + fmaxf(c3 + bb1, 0.f) * w1;
            }
        }
    }
    if (EPI == 2) {
        __syncthreads();
        #pragma unroll
        for (int mi = 0; mi < 2; mi++) {
            #pragma unroll
            for (int q = 0; q < 2; q++) {
                float v = rsum[mi][q];
                v += __shfl_xor_sync(0xffffffffu, v, 1);
                v += __shfl_xor_sync(0xffffffffu, v, 2);
                if ((l & 3) == 0) {
                    int rl = wm * 32 + mi * 16 + (l >> 2) + q * 8;
                    atomicAdd((float*)(smem + SPART + rl * 4), v);
                }
            }
        }
        __syncthreads();
        if (tid < 128)
            g_tpart[(size_t)blockIdx.x * BPROWS + m0 + tid] = *(float*)(smem + SPART + tid * 4);
    }
}

// =============================================================
// Post-GEMM small kernels
// =============================================================
__global__ __launch_bounds__(256) void k_M(const float* __restrict__ I,
                                           float* __restrict__ out)
{
    __shared__ float Gs[32][65];
    __shared__ float Is[40][65];
    const int b = blockIdx.x;
    const int tid = threadIdx.x;
    const int n = tid >> 3;
    const int lg = tid & 7;
    float acc[5] = {0.f, 0.f, 0.f, 0.f, 0.f};

    for (int kt = 0; kt < DV; kt += 64) {
        __syncthreads();
        for (int t = tid; t < 32 * 64; t += 256) {
            int r = t >> 6, c = t & 63;
            Gs[r][c] = g_GUV[(size_t)(b * NN + r) * 2048 + kt + c];
        }
        for (int t = tid; t < 40 * 64; t += 256) {
            int r = t >> 6, c = t & 63;
            Is[r][c] = (r < NLW) ? I[(size_t)b * NLW * DV + (size_t)r * DV + kt + c] : 0.f;
        }
        __syncthreads();
        #pragma unroll 4
        for (int c = 0; c < 64; c++) {
            float g = Gs[n][c];
            #pragma unroll
            for (int s = 0; s < 5; s++)
                acc[s] = fmaf(g, Is[lg + 8 * s][c], acc[s]);
        }
    }
    #pragma unroll
    for (int s = 0; s < 5; s++) {
        int l = lg + 8 * s;
        if (l < NLW) {
            float v = acc[s];
            g_M[b * NNL + n * NLW + l] = v;
            out[1 + b * NNL + n * NLW + l] = v;
        }
    }
}

__global__ void k_A(const float* __restrict__ sm, const float* __restrict__ im)
{
    const int b = blockIdx.x, t = threadIdx.x;
    __shared__ float red[64];
    __shared__ float sms[32];
    if (t < 32) sms[t] = sm[b * NN + t];
    __syncthreads();
    float msum = 0.f;
    for (int o = t; o < NNL; o += 64) msum += g_M[b * NNL + o];
    red[t] = msum;
    if (t < NLW) {
        float a = 0.f;
        #pragma unroll
        for (int n = 0; n < NN; n++)
            a = fmaf(g_M[b * NNL + n * NLW + t], sms[n], a);
        g_Avec[b * NLW + t] = a;
    }
    __syncthreads();
    for (int s = 32; s > 0; s >>= 1) {
        if (t < s) red[t] += red[t + s];
        __syncthreads();
    }
    if (t == 0) {
        g_Msum[b] = red[0];
        float cs = 0.f, ci = 0.f;
        for (int n = 0; n < NN; n++) cs += sms[n];
        for (int l = 0; l < NLW; l++) ci += im[b * NLW + l];
        g_cs[b] = cs;
        g_ci[b] = ci;
    }
}

__global__ void k_sent(const float* __restrict__ im)
{
    const int i = blockIdx.x, j = threadIdx.x;
    __shared__ float As[NLW];
    __shared__ float csI, msI;
    if (j < NLW) As[j] = g_Avec[i * NLW + j];
    if (j == 0) { csI = g_cs[i]; msI = g_Msum[i]; }
    __syncthreads();
    float d = 0.f;
    #pragma unroll
    for (int l = 0; l < NLW; l++) d = fmaf(As[l], im[j * NLW + l], d);
    float cnt = csI * g_ci[j];
    g_sent[i * NB + j] = (cnt > 0.f) ? (d / cnt) : (msI / (float)NNL);
}

__global__ void k_loss(float* __restrict__ out)
{
    const int t = threadIdx.x;
    float mx = -1e30f;
    for (int j = 0; j < NB; j++) mx = fmaxf(mx, g_sent[t * NB + j]);
    float se = 0.f, rs = 0.f;
    for (int j = 0; j < NB; j++) {
        float v = g_sent[t * NB + j];
        se += expf(v - mx);
        rs += v;
    }
    float lr = mx + logf(se);
    float mx2 = -1e30f;
    for (int i = 0; i < NB; i++) mx2 = fmaxf(mx2, g_sent[i * NB + t]);
    float se2 = 0.f;
    for (int i = 0; i < NB; i++) se2 += expf(g_sent[i * NB + t] - mx2);
    float lc = mx2 + logf(se2);
    __shared__ float r1[128], r2[128], r3[128];
    r1[t] = lr; r2[t] = lc; r3[t] = rs;
    __syncthreads();
    for (int s = 64; s > 0; s >>= 1) {
        if (t < s) { r1[t] += r1[t + s]; r2[t] += r2[t + s]; r3[t] += r3[t + s]; }
        __syncthreads();
    }
    if (t == 0) out[0] = r1[0] + r2[0] - 2.f * r3[0] / (float)NB;
}

__global__ void k_text_final(const float* __restrict__ b3, float* __restrict__ out)
{
    int m = blockIdx.x * 256 + threadIdx.x;
    if (m >= BPROWS) return;
    out[1 + NB * NNL + m] = b3[0] + g_tpart[m] + g_tpart[(size_t)BPROWS + m];
}

// =============================================================
extern "C" void kernel_launch(void* const* d_in, const int* in_sizes, int n_in,
                              void* d_out, int out_size)
{
    const float* S   = (const float*)d_in[0];
    const float* I   = (const float*)d_in[1];
    const float* sm  = (const float*)d_in[2];
    const float* im  = (const float*)d_in[3];
    const float* Wg  = (const float*)d_in[4];
    const float* W1  = (const float*)d_in[5];
    const float* b1  = (const float*)d_in[6];
    const float* W2  = (const float*)d_in[7];
    const float* b2  = (const float*)d_in[8];
    const float* W3  = (const float*)d_in[9];
    const float* b3  = (const float*)d_in[10];
    float* out = (float*)d_out;

    cudaFuncSetAttribute(k_gemm_mma<0>, cudaFuncAttributeMaxDynamicSharedMemorySize, SMEM_TOT);
    cudaFuncSetAttribute(k_gemm_mma<1>, cudaFuncAttributeMaxDynamicSharedMemorySize, SMEM_TOT);
    cudaFuncSetAttribute(k_gemm_mma<2>, cudaFuncAttributeMaxDynamicSharedMemorySize, SMEM_TOT);

    // preps
    k_init_pairs<<<1, 512>>>();
    k_prep_Ball<<<2048, 128>>>(Wg, W1);
    k_prep_W1ct<<<512, 128>>>(W1);
    k_prep_W2t<<<512, 128>>>(W2);
    k_prep_S2<<<BNROWS, 128>>>(S);
    k_prep_Pf<<<BPROWS, 128>>>(S);

    // GEMM0: [G|U|V] = S @ [Wg | W1a | W1b]   (bf16 3-term, async operands)
    k_gemm_mma<0><<<dim3(2048 / 256, BNROWS / 128), 512, SMEM_TOT>>>(nullptr, nullptr);

    // image-grounding tail
    k_M<<<NB, 256>>>(I, out);
    k_A<<<NB, 64>>>(sm, im);
    k_sent<<<NB, NB>>>(im);
    k_loss<<<1, NB>>>(out);

    // text path (fp16 single-term, async operands)
    k_gemm_mma<1><<<dim3(HH / 256, BPROWS / 128), 512, SMEM_TOT>>>(b1, nullptr);
    k_gemm_mma<2><<<dim3(HH / 256, BPROWS / 128), 512, SMEM_TOT>>>(b2, W3);
    k_text_final<<<(BPROWS + 255) / 256, 256>>>(b3, out);
}

// round 17
// speedup vs baseline: 1.6118x; 1.0512x over previous
#include <cuda_runtime.h>
#include <cuda_bf16.h>
#include <cuda_fp16.h>
#include <cstdint>
#include <stdint.h>
#include <math.h>

// Problem constants
#define NB 128
#define NN 32
#define NLW 36
#define DS 512
#define DV 1024
#define HH 512
#define NP 496
#define NNL (NN*NLW)      // 1152
#define BNROWS (NB*NN)    // 4096
#define BPROWS (NB*NP)    // 63488
#define NBC 8              // chunks of 64 over K=512

// ---- scratch (__device__ globals; no runtime allocation) ----
__device__ __half g_Ballh[(size_t)2048 * 512];          // [Wg^T;W1a^T;W1b^T] fp16
__device__ __half g_S2h [(size_t)BNROWS * 1024];        // S fp16 (hi|lo)
__device__ __half g_W1ct[(size_t)HH * 512];             // W1c^T fp16
__device__ __half g_W2t [(size_t)HH * 512];             // W2^T  fp16
__device__ __half g_Pf  [(size_t)BPROWS * HH];          // pair products fp16
__device__ __half g_H1  [(size_t)BPROWS * HH];          // H1 fp16
__device__ float g_GUV[(size_t)BNROWS * 2048];          // [G | U | V] fp32
__device__ float g_tpart[(size_t)2 * BPROWS];
__device__ float g_M[NB * NNL];
__device__ float g_Avec[NB * NLW];
__device__ float g_cs[NB];
__device__ float g_ci[NB];
__device__ float g_Msum[NB];
__device__ float g_sent[NB * NB];
__device__ int   g_iu[NP];
__device__ int   g_ju[NP];

// =============================================================
// helpers
// =============================================================
__device__ __forceinline__ uint32_t s2u(const void* p) {
    uint32_t a;
    asm("{ .reg .u64 t; cvta.to.shared.u64 t, %1; cvt.u32.u64 %0, t; }" : "=r"(a) : "l"(p));
    return a;
}
__device__ __forceinline__ void ldsm_x4(uint32_t* r, uint32_t addr) {
    asm volatile("ldmatrix.sync.aligned.m8n8.x4.shared.b16 {%0,%1,%2,%3}, [%4];"
        : "=r"(r[0]), "=r"(r[1]), "=r"(r[2]), "=r"(r[3]) : "r"(addr));
}
__device__ __forceinline__ void mma16816h(float* c, const uint32_t* a, uint32_t b0, uint32_t b1) {
    asm volatile(
        "mma.sync.aligned.m16n8k16.row.col.f32.f16.f16.f32 "
        "{%0,%1,%2,%3}, {%4,%5,%6,%7}, {%8,%9}, {%0,%1,%2,%3};"
        : "+f"(c[0]), "+f"(c[1]), "+f"(c[2]), "+f"(c[3])
        : "r"(a[0]), "r"(a[1]), "r"(a[2]), "r"(a[3]), "r"(b0), "r"(b1));
}
#define CPASYNC16(dst, src) asm volatile("cp.async.cg.shared.global [%0], [%1], 16;" :: "r"(dst), "l"(src))
#define CPCOMMIT()          asm volatile("cp.async.commit_group;" ::: "memory")
#define CPWAIT1()           asm volatile("cp.async.wait_group 1;" ::: "memory")
#define CPWAIT0()           asm volatile("cp.async.wait_group 0;" ::: "memory")

__device__ __forceinline__ uint32_t packh(float a, float b) {
    __half2 h = __halves2half2(__float2half_rn(a), __float2half_rn(b));
    return *(uint32_t*)&h;
}
__device__ __forceinline__ void split2h(float v, __half& h, __half& l) {
    h = __float2half_rn(v);
    l = __float2half_rn(v - __half2float(h));
}

// =============================================================
// Prep kernels
// =============================================================
__global__ void k_init_pairs() {
    int p = threadIdx.x;
    if (p >= NP) return;
    int cum = 0;
    for (int i = 0; i < NN; i++) {
        int cnt = NN - 1 - i;
        if (p < cum + cnt) { g_iu[p] = i; g_ju[p] = i + 1 + (p - cum); return; }
        cum += cnt;
    }
}
__global__ void k_prep_Ball(const float* __restrict__ Wg, const float* __restrict__ W1) {
    int n = blockIdx.x;                 // 2048
    int c0 = threadIdx.x * 4;           // 128 thr
    __half* row = g_Ballh + (size_t)n * 512;
    #pragma unroll
    for (int t = 0; t < 4; t++) {
        int c = c0 + t;
        float w;
        if (n < 1024)      w = Wg[(size_t)c * DV + n];
        else if (n < 1536) w = W1[(size_t)c * HH + (n - 1024)];
        else               w = W1[(size_t)(512 + c) * HH + (n - 1536)];
        row[c] = __float2half_rn(w);
    }
}
__global__ void k_prep_W1ct(const float* __restrict__ W1) {
    int n = blockIdx.x;
    int c0 = threadIdx.x * 4;
    __half* row = g_W1ct + (size_t)n * 512;
    #pragma unroll
    for (int t = 0; t < 4; t++) {
        int c = c0 + t;
        row[c] = __float2half_rn(W1[(size_t)(1024 + c) * HH + n]);
    }
}
__global__ void k_prep_W2t(const float* __restrict__ W2) {
    int n = blockIdx.x;
    int c0 = threadIdx.x * 4;
    __half* row = g_W2t + (size_t)n * 512;
    #pragma unroll
    for (int t = 0; t < 4; t++) {
        int c = c0 + t;
        row[c] = __float2half_rn(W2[(size_t)c * HH + n]);
    }
}
// S -> fp16 hi|lo (A operand of GEMM0)
__global__ void k_prep_S2(const float* __restrict__ S) {
    int r = blockIdx.x;                 // 4096
    int c = threadIdx.x * 4;            // 128 thr
    float4 v = *(const float4*)(S + (size_t)r * DS + c);
    __half h0, l0, h1, l1, h2, l2, h3, l3;
    split2h(v.x, h0, l0); split2h(v.y, h1, l1);
    split2h(v.z, h2, l2); split2h(v.w, h3, l3);
    uint2 hw, lw;
    __half2 a0 = __halves2half2(h0, h1), a1 = __halves2half2(h2, h3);
    __half2 b0 = __halves2half2(l0, l1), b1 = __halves2half2(l2, l3);
    hw.x = *(uint32_t*)&a0; hw.y = *(uint32_t*)&a1;
    lw.x = *(uint32_t*)&b0; lw.y = *(uint32_t*)&b1;
    *(uint2*)(g_S2h + (size_t)r * 1024 + c)       = hw;
    *(uint2*)(g_S2h + (size_t)r * 1024 + 512 + c) = lw;
}
// pair products -> fp16, batch-SMEM tiled (grid: (NB, 4))
__global__ __launch_bounds__(256) void k_prep_Pf(const float* __restrict__ S) {
    extern __shared__ float Ss[];       // 32 x 512 fp32 = 64 KB
    const int b = blockIdx.x;
    const int q = blockIdx.y;           // quarter: 124 pairs each
    const float* Sb = S + (size_t)b * NN * DS;
    for (int i = threadIdx.x; i < NN * DS / 4; i += 256)
        ((float4*)Ss)[i] = ((const float4*)Sb)[i];
    __syncthreads();
    const int c = threadIdx.x * 2;      // 0..510
    const int p0 = q * 124;
    for (int p = p0; p < p0 + 124; p++) {
        const float* ri = Ss + g_iu[p] * DS;
        const float* rj = Ss + g_ju[p] * DS;
        float2 a = *(const float2*)(ri + c);
        float2 d = *(const float2*)(rj + c);
        *(uint32_t*)(g_Pf + (size_t)(b * NP + p) * HH + c) = packh(a.x * d.x, a.y * d.y);
    }
}

// =============================================================
// Unified fp16 HMMA GEMM — all operands prematerialized, via cp.async.
// BM=128, BN=256, chunk K=64, 512 threads (16 warps, 4x4), warp tile 32x64.
// EPI 0 (2 terms): A=g_S2h(hi|lo), B=g_Ballh -> g_GUV fp32 (N=2048)
// EPI 1 (1 term):  A=g_Pf,  B=g_W1ct; epi: +U+V+b1, relu -> g_H1
// EPI 2 (1 term):  A=g_H1,  B=g_W2t;  epi: relu(+b2)·W3 -> g_tpart
// =============================================================
#define ARS 72                         // smem row stride in 2B elems (144 B)
#define ATILE (128 * ARS * 2)          // 18432
#define BTILE (256 * ARS * 2)          // 36864
#define AHI(s) ((uint32_t)((s) * 2 * ATILE))
#define ALO(s) ((uint32_t)((s) * 2 * ATILE + ATILE))
#define BOFF2(s) ((uint32_t)(4 * ATILE + (s) * BTILE))
#define SPART    ((uint32_t)(4 * ATILE + 2 * BTILE))    // 147456
#define SMEM_TOT (4 * ATILE + 2 * BTILE + 512)          // 147968

template<int EPI>
__global__ __launch_bounds__(512, 1)
void k_gemm_mma(const float* __restrict__ bias, const float* __restrict__ W3)
{
    extern __shared__ char smem[];
    const uint32_t sb = s2u(smem);
    const int tid = threadIdx.x;
    const int m0 = blockIdx.y * 128;
    const int n0 = blockIdx.x * 256;

    // ---- async A loader: thread t -> rows rA0=t>>3, rA0+64; k-cols (t&7)*8
    const int rA0 = tid >> 3;
    const int rA1 = rA0 + 64;
    const int kcA = (tid & 7) * 8;
    const uint32_t aDst0 = (uint32_t)(rA0 * (ARS * 2) + kcA * 2);
    const uint32_t aDst1 = (uint32_t)(rA1 * (ARS * 2) + kcA * 2);

    auto fillA = [&](int bc, int s) {
        if (EPI == 0) {
            const __half* s0 = g_S2h + (size_t)(m0 + rA0) * 1024 + bc * 64 + kcA;
            const __half* s1 = g_S2h + (size_t)(m0 + rA1) * 1024 + bc * 64 + kcA;
            CPASYNC16(sb + AHI(s) + aDst0, s0);
            CPASYNC16(sb + AHI(s) + aDst1, s1);
            CPASYNC16(sb + ALO(s) + aDst0, s0 + 512);
            CPASYNC16(sb + ALO(s) + aDst1, s1 + 512);
        } else {
            const __half* base = (EPI == 1) ? g_Pf : g_H1;
            CPASYNC16(sb + AHI(s) + aDst0, base + (size_t)(m0 + rA0) * HH + bc * 64 + kcA);
            CPASYNC16(sb + AHI(s) + aDst1, base + (size_t)(m0 + rA1) * HH + bc * 64 + kcA);
        }
    };
    const __half* __restrict__ Bh =
        (EPI == 0) ? g_Ballh : (EPI == 1) ? g_W1ct : g_W2t;
    auto fillB = [&](int bc, int buf) {
        #pragma unroll
        for (int rep = 0; rep < 4; rep++) {
            int gg = tid + rep * 512;
            int rb = gg >> 3, cb = (gg & 7) * 8;
            uint32_t dst = sb + BOFF2(buf) + (uint32_t)(rb * (ARS * 2) + cb * 2);
            const __half* src = Bh + (size_t)(n0 + rb) * 512 + bc * 64 + cb;
            CPASYNC16(dst, src);
        }
    };
    auto issueGroup = [&](int bc, int s) {
        fillA(bc, s);
        fillB(bc, s);
        CPCOMMIT();
    };

    // ---- warp layout
    const int wid = tid >> 5;
    const int wm = wid >> 2;
    const int wn = wid & 3;
    const int l = tid & 31;

    float acc[2][8][4];
    #pragma unroll
    for (int mi = 0; mi < 2; mi++)
        #pragma unroll
        for (int nb = 0; nb < 8; nb++)
            #pragma unroll
            for (int q = 0; q < 4; q++) acc[mi][nb][q] = 0.f;

    if (EPI == 2) {
        if (tid < 128) *(float*)(smem + SPART + tid * 4) = 0.f;
    }

    const uint32_t lrow = (uint32_t)(l & 15);
    const uint32_t lcol8 = (uint32_t)((l >> 4) * 8);

    // ---- depth-2 pipeline
    issueGroup(0, 0);
    issueGroup(1, 1);

    for (int bc = 0; bc < NBC; bc++) {
        const int s = bc & 1;
        if (bc < NBC - 1) { CPWAIT1(); } else { CPWAIT0(); }
        __syncthreads();

        const uint32_t ahibase = sb + AHI(s);
        const uint32_t alobase = sb + ALO(s);
        const uint32_t bbase   = sb + BOFF2(s);
        #pragma unroll
        for (int ks = 0; ks < 4; ks++) {
            const uint32_t arow = ((uint32_t)(wm * 32) + lrow) * (ARS * 2)
                                + ((uint32_t)(ks * 16) + lcol8) * 2;
            const uint32_t brow = ((uint32_t)(wn * 64) + lrow) * (ARS * 2)
                                + ((uint32_t)(ks * 16) + lcol8) * 2;
            uint32_t ah[2][4], al[2][4], bf[4][4];
            #pragma unroll
            for (int mi = 0; mi < 2; mi++) {
                ldsm_x4(ah[mi], ahibase + arow + (uint32_t)(mi * 16 * ARS * 2));
                if (EPI == 0)
                    ldsm_x4(al[mi], alobase + arow + (uint32_t)(mi * 16 * ARS * 2));
            }
            #pragma unroll
            for (int np = 0; np < 4; np++)
                ldsm_x4(bf[np], bbase + brow + (uint32_t)(np * 16 * ARS * 2));
            #pragma unroll
            for (int mi = 0; mi < 2; mi++)
                #pragma unroll
                for (int nb = 0; nb < 8; nb++) {
                    int np = nb >> 1, hf = nb & 1;
                    mma16816h(acc[mi][nb], ah[mi], bf[np][hf], bf[np][2 + hf]);
                    if (EPI == 0)
                        mma16816h(acc[mi][nb], al[mi], bf[np][hf], bf[np][2 + hf]);
                }
        }
        __syncthreads();
        if (bc + 2 < NBC) issueGroup(bc + 2, s);
    }

    // ---- epilogue (register accumulators) ----
    float rsum[2][2] = {{0.f, 0.f}, {0.f, 0.f}};
    #pragma unroll
    for (int mi = 0; mi < 2; mi++) {
        const int rl = wm * 32 + mi * 16 + (l >> 2);
        const int row0 = m0 + rl;
        const int row1 = row0 + 8;
        const float *U0 = nullptr, *V0 = nullptr, *U1 = nullptr, *V1 = nullptr;
        if (EPI == 1) {
            int b0_ = row0 / NP, p0_ = row0 - b0_ * NP;
            int b1_ = row1 / NP, p1_ = row1 - b1_ * NP;
            U0 = g_GUV + (size_t)(b0_ * NN + g_iu[p0_]) * 2048 + 1024;
            V0 = g_GUV + (size_t)(b0_ * NN + g_ju[p0_]) * 2048 + 1536;
            U1 = g_GUV + (size_t)(b1_ * NN + g_iu[p1_]) * 2048 + 1024;
            V1 = g_GUV + (size_t)(b1_ * NN + g_ju[p1_]) * 2048 + 1536;
        }
        #pragma unroll
        for (int nb = 0; nb < 8; nb++) {
            const int col = n0 + wn * 64 + nb * 8 + (l & 3) * 2;
            float c0 = acc[mi][nb][0], c1 = acc[mi][nb][1];
            float c2 = acc[mi][nb][2], c3 = acc[mi][nb][3];
            if (EPI == 0) {
                float2 u = {c0, c1}, v = {c2, c3};
                *(float2*)&g_GUV[(size_t)row0 * 2048 + col] = u;
                *(float2*)&g_GUV[(size_t)row1 * 2048 + col] = v;
            } else if (EPI == 1) {
                float v0 = fmaxf(c0 + U0[col]     + V0[col]     + bias[col],     0.f);
                float v1 = fmaxf(c1 + U0[col + 1] + V0[col + 1] + bias[col + 1], 0.f);
                float v2 = fmaxf(c2 + U1[col]     + V1[col]     + bias[col],     0.f);
                float v3 = fmaxf(c3 + U1[col + 1] + V1[col + 1] + bias[col + 1], 0.f);
                *(uint32_t*)&g_H1[(size_t)row0 * HH + col] = packh(v0, v1);
                *(uint32_t*)&g_H1[(size_t)row1 * HH + col] = packh(v2, v3);
            } else {
                float w0 = W3[col], w1 = W3[col + 1];
                float bb0 = bias[col], bb1 = bias[col + 1];
                rsum[mi][0] += fmaxf(c0 + bb0, 0.f) * w0 + fmaxf(c1 + bb1, 0.f) * w1;
                rsum[mi][1] += fmaxf(c2 + bb0, 0.f) * w0 + fmaxf(c3 + bb1, 0.f) * w1;
            }
        }
    }
    if (EPI == 2) {
        __syncthreads();
        #pragma unroll
        for (int mi = 0; mi < 2; mi++) {
            #pragma unroll
            for (int q = 0; q < 2; q++) {
                float v = rsum[mi][q];
                v += __shfl_xor_sync(0xffffffffu, v, 1);
                v += __shfl_xor_sync(0xffffffffu, v, 2);
                if ((l & 3) == 0) {
                    int rl = wm * 32 + mi * 16 + (l >> 2) + q * 8;
                    atomicAdd((float*)(smem + SPART + rl * 4), v);
                }
            }
        }
        __syncthreads();
        if (tid < 128)
            g_tpart[(size_t)blockIdx.x * BPROWS + m0 + tid] = *(float*)(smem + SPART + tid * 4);
    }
}

// =============================================================
// Post-GEMM small kernels
// =============================================================
__global__ __launch_bounds__(256) void k_M(const float* __restrict__ I,
                                           float* __restrict__ out)
{
    __shared__ float Gs[32][65];
    __shared__ float Is[40][65];
    const int b = blockIdx.x;
    const int tid = threadIdx.x;
    const int n = tid >> 3;
    const int lg = tid & 7;
    float acc[5] = {0.f, 0.f, 0.f, 0.f, 0.f};

    for (int kt = 0; kt < DV; kt += 64) {
        __syncthreads();
        for (int t = tid; t < 32 * 64; t += 256) {
            int r = t >> 6, c = t & 63;
            Gs[r][c] = g_GUV[(size_t)(b * NN + r) * 2048 + kt + c];
        }
        for (int t = tid; t < 40 * 64; t += 256) {
            int r = t >> 6, c = t & 63;
            Is[r][c] = (r < NLW) ? I[(size_t)b * NLW * DV + (size_t)r * DV + kt + c] : 0.f;
        }
        __syncthreads();
        #pragma unroll 4
        for (int c = 0; c < 64; c++) {
            float g = Gs[n][c];
            #pragma unroll
            for (int s = 0; s < 5; s++)
                acc[s] = fmaf(g, Is[lg + 8 * s][c], acc[s]);
        }
    }
    #pragma unroll
    for (int s = 0; s < 5; s++) {
        int l = lg + 8 * s;
        if (l < NLW) {
            float v = acc[s];
            g_M[b * NNL + n * NLW + l] = v;
            out[1 + b * NNL + n * NLW + l] = v;
        }
    }
}

__global__ void k_A(const float* __restrict__ sm, const float* __restrict__ im)
{
    const int b = blockIdx.x, t = threadIdx.x;
    __shared__ float red[64];
    __shared__ float sms[32];
    if (t < 32) sms[t] = sm[b * NN + t];
    __syncthreads();
    float msum = 0.f;
    for (int o = t; o < NNL; o += 64) msum += g_M[b * NNL + o];
    red[t] = msum;
    if (t < NLW) {
        float a = 0.f;
        #pragma unroll
        for (int n = 0; n < NN; n++)
            a = fmaf(g_M[b * NNL + n * NLW + t], sms[n], a);
        g_Avec[b * NLW + t] = a;
    }
    __syncthreads();
    for (int s = 32; s > 0; s >>= 1) {
        if (t < s) red[t] += red[t + s];
        __syncthreads();
    }
    if (t == 0) {
        g_Msum[b] = red[0];
        float cs = 0.f, ci = 0.f;
        for (int n = 0; n < NN; n++) cs += sms[n];
        for (int l = 0; l < NLW; l++) ci += im[b * NLW + l];
        g_cs[b] = cs;
        g_ci[b] = ci;
    }
}

__global__ void k_sent(const float* __restrict__ im)
{
    const int i = blockIdx.x, j = threadIdx.x;
    __shared__ float As[NLW];
    __shared__ float csI, msI;
    if (j < NLW) As[j] = g_Avec[i * NLW + j];
    if (j == 0) { csI = g_cs[i]; msI = g_Msum[i]; }
    __syncthreads();
    float d = 0.f;
    #pragma unroll
    for (int l = 0; l < NLW; l++) d = fmaf(As[l], im[j * NLW + l], d);
    float cnt = csI * g_ci[j];
    g_sent[i * NB + j] = (cnt > 0.f) ? (d / cnt) : (msI / (float)NNL);
}

__global__ void k_loss(float* __restrict__ out)
{
    const int t = threadIdx.x;
    float mx = -1e30f;
    for (int j = 0; j < NB; j++) mx = fmaxf(mx, g_sent[t * NB + j]);
    float se = 0.f, rs = 0.f;
    for (int j = 0; j < NB; j++) {
        float v = g_sent[t * NB + j];
        se += expf(v - mx);
        rs += v;
    }
    float lr = mx + logf(se);
    float mx2 = -1e30f;
    for (int i = 0; i < NB; i++) mx2 = fmaxf(mx2, g_sent[i * NB + t]);
    float se2 = 0.f;
    for (int i = 0; i < NB; i++) se2 += expf(g_sent[i * NB + t] - mx2);
    float lc = mx2 + logf(se2);
    __shared__ float r1[128], r2[128], r3[128];
    r1[t] = lr; r2[t] = lc; r3[t] = rs;
    __syncthreads();
    for (int s = 64; s > 0; s >>= 1) {
        if (t < s) { r1[t] += r1[t + s]; r2[t] += r2[t + s]; r3[t] += r3[t + s]; }
        __syncthreads();
    }
    if (t == 0) out[0] = r1[0] + r2[0] - 2.f * r3[0] / (float)NB;
}

__global__ void k_text_final(const float* __restrict__ b3, float* __restrict__ out)
{
    int m = blockIdx.x * 256 + threadIdx.x;
    if (m >= BPROWS) return;
    out[1 + NB * NNL + m] = b3[0] + g_tpart[m] + g_tpart[(size_t)BPROWS + m];
}

// =============================================================
extern "C" void kernel_launch(void* const* d_in, const int* in_sizes, int n_in,
                              void* d_out, int out_size)
{
    const float* S   = (const float*)d_in[0];
    const float* I   = (const float*)d_in[1];
    const float* sm  = (const float*)d_in[2];
    const float* im  = (const float*)d_in[3];
    const float* Wg  = (const float*)d_in[4];
    const float* W1  = (const float*)d_in[5];
    const float* b1  = (const float*)d_in[6];
    const float* W2  = (const float*)d_in[7];
    const float* b2  = (const float*)d_in[8];
    const float* W3  = (const float*)d_in[9];
    const float* b3  = (const float*)d_in[10];
    float* out = (float*)d_out;

    cudaFuncSetAttribute(k_gemm_mma<0>, cudaFuncAttributeMaxDynamicSharedMemorySize, SMEM_TOT);
    cudaFuncSetAttribute(k_gemm_mma<1>, cudaFuncAttributeMaxDynamicSharedMemorySize, SMEM_TOT);
    cudaFuncSetAttribute(k_gemm_mma<2>, cudaFuncAttributeMaxDynamicSharedMemorySize, SMEM_TOT);
    cudaFuncSetAttribute(k_prep_Pf, cudaFuncAttributeMaxDynamicSharedMemorySize, NN * DS * 4);

    // preps
    k_init_pairs<<<1, 512>>>();
    k_prep_Ball<<<2048, 128>>>(Wg, W1);
    k_prep_W1ct<<<512, 128>>>(W1);
    k_prep_W2t<<<512, 128>>>(W2);
    k_prep_S2<<<BNROWS, 128>>>(S);
    k_prep_Pf<<<dim3(NB, 4), 256, NN * DS * 4>>>(S);

    // GEMM0: [G|U|V] = S @ [Wg | W1a | W1b]   (fp16 2-term)
    k_gemm_mma<0><<<dim3(2048 / 256, BNROWS / 128), 512, SMEM_TOT>>>(nullptr, nullptr);

    // image-grounding tail
    k_M<<<NB, 256>>>(I, out);
    k_A<<<NB, 64>>>(sm, im);
    k_sent<<<NB, NB>>>(im);
    k_loss<<<1, NB>>>(out);

    // text path (fp16 single-term)
    k_gemm_mma<1><<<dim3(HH / 256, BPROWS / 128), 512, SMEM_TOT>>>(b1, nullptr);
    k_gemm_mma<2><<<dim3(HH / 256, BPROWS / 128), 512, SMEM_TOT>>>(b2, W3);
    k_text_final<<<(BPROWS + 255) / 256, 256>>>(b3, out);
}